// round 16
// baseline (speedup 1.0000x reference)
#include <cuda_runtime.h>
#include <cuda_bf16.h>
#include <math.h>

#define H      64
#define DIN    128
#define EPSBN  1e-5f
#define MAXN   50048
#define MAXE   1200128
#define MAXG   64

// ---------------- scratch (static __device__, no runtime allocs) ----------------
// Invariant: g_indeg, g_pool, g_gcnt are ZERO at entry to kernel_launch and are
// re-zeroed before the launch ends (deferred zeroing).
// Interleaved gather rows (256B/node, 16B granule per 4 channels):
//   granule l of node r = { streamA pair(4ch as 2x bf162) | streamB pair }
//   g_h2x : A = dinv_r * h_r, B = h_r          (layer-1 gather source)
//   g_hh2x: A = dinv_r * hg_r, B = hs_r        (layer-2 gather source)
__device__ uint4          g_h2x [MAXN * 16];
__device__ uint4          g_hh2x[MAXN * 16];
__device__ __nv_bfloat162 g_h16 [MAXN * 32];  // plain h (SAGE L1 Wr operand)
__device__ __nv_bfloat162 g_hs16[MAXN * 32];  // plain hs (SAGE L2 Wr operand)
__device__ __nv_bfloat162 g_aG16[MAXN * 32];  // gcn agg scratch
__device__ __nv_bfloat162 g_aS16[MAXN * 32];  // sage agg scratch
__device__ __nv_bfloat16  g_Wt  [32768];      // prepped weights (transposed+swizzled bf16)
__device__ float g_esc[320], g_esh[320];      // epilogue scale/shift
__device__ int   g_indeg[MAXN];
__device__ int   g_epos [MAXE];               // edge slot within its dst row
__device__ int   g_rowptr[MAXN + 1];
__device__ int   g_col  [MAXE];
__device__ float g_dinv [MAXN];
__device__ float g_pool [MAXG * 2 * H];
__device__ int   g_gcnt [MAXG];
__device__ int   g_scanbuf[MAXN];
__device__ int   g_blocksums[256];

__device__ __forceinline__ unsigned pk(float a, float b) {
    __nv_bfloat162 t = __floats2bfloat162_rn(a, b);
    return *(unsigned*)&t;
}
__device__ __forceinline__ float2 upk(unsigned u) {
    return __bfloat1622float2(*(__nv_bfloat162*)&u);
}

// ---------------- deg (+ edge slot) + weight prep + epilogue consts ----------------
__global__ void k_deg_prep(const int* __restrict__ dst, const int* __restrict__ batch,
                           const float* __restrict__ W_in, const float* __restrict__ gcn_W,
                           const float* __restrict__ sg_Wl, const float* __restrict__ sg_Wr,
                           const float* __restrict__ b_in, const float* __restrict__ gcn_b,
                           const float* __restrict__ gcn_bn, const float* __restrict__ sg_b,
                           const float* __restrict__ sg_bn, int E, int N) {
    int i = blockIdx.x * 256 + threadIdx.x;
    if (i < E) g_epos[i] = atomicAdd(&g_indeg[dst[i]], 1);
    if (i < N) atomicAdd(&g_gcnt[batch[i]], 1);
    if (i < 32768) {
        int e = i, nn, k, K, base; float w;
        if (e < 8192)       { K = 128; base = 0;     nn = e >> 7; k = e & 127; w = W_in[k * 64 + nn]; }
        else if (e < 12288) { K = 64;  base = 8192;  int l = e - 8192;  nn = l >> 6; k = l & 63;  w = gcn_W[k * 64 + nn]; }
        else if (e < 16384) { K = 64;  base = 12288; int l = e - 12288; nn = l >> 6; k = l & 63;  w = gcn_W[4096 + k * 64 + nn]; }
        else if (e < 24576) { K = 128; base = 16384; int l = e - 16384; nn = l >> 7; k = l & 127;
                              w = (k < 64) ? sg_Wl[k * 64 + nn] : sg_Wr[(k - 64) * 64 + nn]; }
        else                { K = 128; base = 24576; int l = e - 24576; nn = l >> 7; k = l & 127;
                              w = (k < 64) ? sg_Wl[4096 + k * 64 + nn] : sg_Wr[4096 + (k - 64) * 64 + nn]; }
        int word = (k >> 1) ^ ((nn & 7) << 2);
        g_Wt[base + nn * K + word * 2 + (k & 1)] = __float2bfloat16(w);
    }
    if (blockIdx.x == 0 && threadIdx.x < 64) {
        int c = threadIdx.x;
        g_esc[c] = 1.f; g_esh[c] = b_in[c];
        for (int l = 0; l < 2; l++) {
            const float* bn = gcn_bn + l * 256;
            float sc = bn[c] * rsqrtf(bn[192 + c] + EPSBN);
            g_esc[(1 + l) * 64 + c] = sc;
            g_esh[(1 + l) * 64 + c] = (gcn_b[l * 64 + c] - bn[128 + c]) * sc + bn[64 + c];
            const float* bs = sg_bn + l * 256;
            float sc2 = bs[c] * rsqrtf(bs[192 + c] + EPSBN);
            g_esc[(3 + l) * 64 + c] = sc2;
            g_esh[(3 + l) * 64 + c] = (sg_b[l * 64 + c] - bs[128 + c]) * sc2 + bs[64 + c];
        }
    }
}

// ---------------- two-pass scan (parallel, no cross-block waits) ----------------
__global__ void k_scan1(int N) {
    __shared__ int sh[256];
    int t = threadIdx.x;
    int i = blockIdx.x * 256 + t;
    int v = (i < N) ? g_indeg[i] : 0;
    sh[t] = v; __syncthreads();
#pragma unroll
    for (int off = 1; off < 256; off <<= 1) {
        int a = 0;
        if (t >= off) a = sh[t - off];
        __syncthreads();
        sh[t] += a;
        __syncthreads();
    }
    if (i < N) {
        g_scanbuf[i] = sh[t];
        g_dinv[i] = rsqrtf((float)(v + 1));
    }
    if (t == 255) g_blocksums[blockIdx.x] = sh[255];
}

__global__ void k_scanB(int nb, int N) {
    __shared__ int sh[256];
    int t = threadIdx.x;
    int v = (t < nb) ? g_blocksums[t] : 0;
    sh[t] = v; __syncthreads();
#pragma unroll
    for (int off = 1; off < 256; off <<= 1) {
        int a = 0;
        if (t >= off) a = sh[t - off];
        __syncthreads();
        sh[t] += a;
        __syncthreads();
    }
    int myoff = sh[blockIdx.x] - g_blocksums[blockIdx.x];
    int i = blockIdx.x * 256 + t;
    if (i < N) g_rowptr[i + 1] = g_scanbuf[i] + myoff;
    if (i == 0) g_rowptr[0] = 0;
}

// ---------------- mma asm helper ----------------
#define MMA16816(c, a0, a1, a2, a3, b0, b1) \
    asm volatile( \
        "mma.sync.aligned.m16n8k16.row.col.f32.bf16.bf16.f32 " \
        "{%0,%1,%2,%3}, {%4,%5,%6,%7}, {%8,%9}, {%0,%1,%2,%3};" \
        : "+f"((c)[0]), "+f"((c)[1]), "+f"((c)[2]), "+f"((c)[3]) \
        : "r"(a0), "r"(a1), "r"(a2), "r"(a3), "r"(b0), "r"(b1))

// ---------------- fused: CSR fill + input projection (independent work) ----------------
// Blocks [0, nbM): h = relu(x @ W_in + b_in). BM=64, N split across 8 warps.
//   Epilogue writes interleaved h2x {dinv*h|h} + plain h16.
// Blocks [nbM, ...): CSR fill, plain 4B col (no atomics, no gathers).
__global__ void __launch_bounds__(256)
k_fill_mma(const int* __restrict__ src, const int* __restrict__ dst, int E, int nbM,
           const float* __restrict__ X, const __nv_bfloat16* __restrict__ Wt,
           const float* __restrict__ esc, const float* __restrict__ esh,
           unsigned* __restrict__ h2u, __nv_bfloat162* __restrict__ out16, int n) {
    __shared__ __align__(16) __nv_bfloat16 As[64 * 128];
    if ((int)blockIdx.x >= nbM) {
        int e = (blockIdx.x - nbM) * 256 + threadIdx.x;
        if (e < E) {
            int d = dst[e];
            g_col[g_rowptr[d] + g_epos[e]] = src[e];
        }
        return;
    }
    const int tid = threadIdx.x;
    const int r0 = blockIdx.x * 64;
    for (int i = tid; i < 64 * 32; i += 256) {
        int row = i >> 5, c4 = i & 31;
        int r = r0 + row;
        float4 v = make_float4(0.f, 0.f, 0.f, 0.f);
        if (r < n) v = *(const float4*)(X + (long)r * 128 + c4 * 4);
        int hoff = row * 128 + ((c4 * 4) ^ ((row & 7) << 3));
        __nv_bfloat162* p = (__nv_bfloat162*)&As[hoff];
        p[0] = __floats2bfloat162_rn(v.x, v.y);
        p[1] = __floats2bfloat162_rn(v.z, v.w);
    }
    __syncthreads();
    const int w = tid >> 5, lane = tid & 31;
    const int g = lane >> 2, t = lane & 3;
    const int wm = w & 3, half = w >> 2;
    const int rA = wm * 16 + g;
    const unsigned* A32 = (const unsigned*)As;
    const unsigned* B32 = (const unsigned*)Wt;  // global, stays hot in L1
    float c[4][4] = {};
#pragma unroll
    for (int k0 = 0; k0 < 128; k0 += 16) {
        int kw0 = ((k0 >> 1) + t) ^ (g << 2), kw1 = ((k0 >> 1) + t + 4) ^ (g << 2);
        unsigned a0 = A32[rA * 64 + kw0], a1 = A32[(rA + 8) * 64 + kw0];
        unsigned a2 = A32[rA * 64 + kw1], a3 = A32[(rA + 8) * 64 + kw1];
#pragma unroll
        for (int nt = 0; nt < 4; nt++) {
            int ncol = half * 32 + nt * 8 + g;
            unsigned b0 = B32[ncol * 64 + kw0], b1 = B32[ncol * 64 + kw1];
            MMA16816(c[nt], a0, a1, a2, a3, b0, b1);
        }
    }
    int row0 = r0 + wm * 16 + g, row1 = row0 + 8;
    float dv0 = (row0 < n) ? g_dinv[row0] : 1.f;
    float dv1 = (row1 < n) ? g_dinv[row1] : 1.f;
#pragma unroll
    for (int nt = 0; nt < 4; nt++) {
        int col = half * 32 + nt * 8 + 2 * t;
        int p = col >> 1;
        int gofs = (p >> 1) * 4 + (p & 1);       // granule uint offset for stream A
        float s0 = esc[col], s1 = esc[col + 1], h0 = esh[col], h1 = esh[col + 1];
        float v00 = fmaxf(c[nt][0] * s0 + h0, 0.f);
        float v01 = fmaxf(c[nt][1] * s1 + h1, 0.f);
        float v10 = fmaxf(c[nt][2] * s0 + h0, 0.f);
        float v11 = fmaxf(c[nt][3] * s1 + h1, 0.f);
        if (row0 < n) {
            h2u[row0 * 64 + gofs]     = pk(v00 * dv0, v01 * dv0);
            h2u[row0 * 64 + gofs + 2] = pk(v00, v01);
            out16[row0 * 32 + p]      = __floats2bfloat162_rn(v00, v01);
        }
        if (row1 < n) {
            h2u[row1 * 64 + gofs]     = pk(v10 * dv1, v11 * dv1);
            h2u[row1 * 64 + gofs + 2] = pk(v10, v11);
            out16[row1 * 32 + p]      = __floats2bfloat162_rn(v10, v11);
        }
    }
}

// ---------------- aggregations: 16 lanes per node, 2 nodes per warp ----------------
// One uint4 row load per neighbor carries BOTH streams (A=weighted, B=plain).
// Layer 1: aG[d] = dinv_d*(sum dinv_s*h_s + dinv_d*h_d);  aS[d] = mean h_s
__global__ void __launch_bounds__(256)
k_agg1(const uint4* __restrict__ hx,
       __nv_bfloat162* __restrict__ aG, __nv_bfloat162* __restrict__ aS, int n) {
    int warp = threadIdx.x >> 5, lane = threadIdx.x & 31;
    int half = lane >> 4, l = lane & 15;
    int d = blockIdx.x * 16 + warp * 2 + half;
    bool dok = d < n;
    int beg = 0, end = 0;
    if (dok) { beg = g_rowptr[d]; end = g_rowptr[d + 1]; }
    int cnt = end - beg;
    int mc = __reduce_max_sync(0xffffffffu, cnt);
    float g0 = 0.f, g1 = 0.f, g2 = 0.f, g3 = 0.f;
    float s0 = 0.f, s1 = 0.f, s2 = 0.f, s3 = 0.f;
    for (int k = 0; k < mc; k += 8) {
#pragma unroll
        for (int u = 0; u < 8; u++) {
            int idx = k + u;
            bool v = idx < cnt;
            int s = 0;
            if (v) s = g_col[beg + idx];
            float vm = v ? 1.f : 0.f;
            uint4 q = hx[s * 16 + l];
            float2 pa0 = upk(q.x), pa1 = upk(q.y);   // dinv_s * h_s
            float2 pb0 = upk(q.z), pb1 = upk(q.w);   // h_s
            g0 += vm * pa0.x; g1 += vm * pa0.y; g2 += vm * pa1.x; g3 += vm * pa1.y;
            s0 += vm * pb0.x; s1 += vm * pb0.y; s2 += vm * pb1.x; s3 += vm * pb1.y;
        }
    }
    if (!dok) return;
    float wd = g_dinv[d];
    uint4 qd = hx[d * 16 + l];
    float2 pd0 = upk(qd.x), pd1 = upk(qd.y);         // dinv_d * h_d
    g0 = (g0 + pd0.x) * wd; g1 = (g1 + pd0.y) * wd;
    g2 = (g2 + pd1.x) * wd; g3 = (g3 + pd1.y) * wd;
    float inv = 1.f / fmaxf((float)cnt, 1.f);
    uint2 og, os;
    og.x = pk(g0, g1); og.y = pk(g2, g3);
    os.x = pk(s0 * inv, s1 * inv); os.y = pk(s2 * inv, s3 * inv);
    ((uint2*)aG)[d * 16 + l] = og;
    ((uint2*)aS)[d * 16 + l] = os;
}

// Layer 2: hh2x rows {dinv*hg | hs}.  aG[d]=dinv_d*(sum hgA_s + hgA_d); aS = mean hs_s
__global__ void __launch_bounds__(256)
k_agg2(const uint4* __restrict__ hx,
       __nv_bfloat162* __restrict__ aG, __nv_bfloat162* __restrict__ aS, int n) {
    int warp = threadIdx.x >> 5, lane = threadIdx.x & 31;
    int half = lane >> 4, l = lane & 15;
    int d = blockIdx.x * 16 + warp * 2 + half;
    bool dok = d < n;
    int beg = 0, end = 0;
    if (dok) { beg = g_rowptr[d]; end = g_rowptr[d + 1]; }
    int cnt = end - beg;
    int mc = __reduce_max_sync(0xffffffffu, cnt);
    float g0 = 0.f, g1 = 0.f, g2 = 0.f, g3 = 0.f;
    float s0 = 0.f, s1 = 0.f, s2 = 0.f, s3 = 0.f;
    for (int k = 0; k < mc; k += 8) {
#pragma unroll
        for (int u = 0; u < 8; u++) {
            int idx = k + u;
            bool v = idx < cnt;
            int s = 0;
            if (v) s = g_col[beg + idx];
            float vm = v ? 1.f : 0.f;
            uint4 q = hx[s * 16 + l];
            float2 pa0 = upk(q.x), pa1 = upk(q.y);   // dinv_s * hg_s
            float2 pb0 = upk(q.z), pb1 = upk(q.w);   // hs_s
            g0 += vm * pa0.x; g1 += vm * pa0.y; g2 += vm * pa1.x; g3 += vm * pa1.y;
            s0 += vm * pb0.x; s1 += vm * pb0.y; s2 += vm * pb1.x; s3 += vm * pb1.y;
        }
    }
    if (!dok) return;
    float wd = g_dinv[d];
    uint4 qd = hx[d * 16 + l];
    float2 pd0 = upk(qd.x), pd1 = upk(qd.y);
    g0 = (g0 + pd0.x) * wd; g1 = (g1 + pd0.y) * wd;
    g2 = (g2 + pd1.x) * wd; g3 = (g3 + pd1.y) * wd;
    float inv = 1.f / fmaxf((float)cnt, 1.f);
    uint2 og, os;
    og.x = pk(g0, g1); og.y = pk(g2, g3);
    os.x = pk(s0 * inv, s1 * inv); os.y = pk(s2 * inv, s3 * inv);
    ((uint2*)aG)[d * 16 + l] = og;
    ((uint2*)aS)[d * 16 + l] = os;
}

// ---------------- dual MMA: warps 0-3 GCN (K=64), warps 4-7 SAGE (K=128) ----------------
// LAYER==1: writes interleaved hh2u {dinv*hg|hs} + plain hs16 (L2 Wr operand).
// LAYER==2: no feature output; pools post-BN fp32 values per graph (batch sorted).
template<int LAYER>
__global__ void __launch_bounds__(256)
k_mma_dual(const __nv_bfloat162* __restrict__ aG,
           const __nv_bfloat162* __restrict__ aS,
           const __nv_bfloat162* __restrict__ Aprev,
           unsigned* __restrict__ hh2u,
           __nv_bfloat162* __restrict__ hs16,
           const __nv_bfloat16* __restrict__ Wg,
           const __nv_bfloat16* __restrict__ Wsg,
           const float* __restrict__ escG, const float* __restrict__ eshG,
           const float* __restrict__ escS, const float* __restrict__ eshS,
           const int* __restrict__ batch, int n) {
    __shared__ __align__(16) char sbuf[49152];
    __nv_bfloat16* aG_s  = (__nv_bfloat16*)sbuf;            // 8KB
    __nv_bfloat16* aSh_s = (__nv_bfloat16*)(sbuf + 8192);   // 16KB
    __nv_bfloat16* Wg_s  = (__nv_bfloat16*)(sbuf + 24576);  // 8KB
    __nv_bfloat16* Wsg_s = (__nv_bfloat16*)(sbuf + 32768);  // 16KB
    const int tid = threadIdx.x;
    const int r0 = blockIdx.x * 64;

    {
        const uint4* s1 = (const uint4*)Wg;  uint4* d1 = (uint4*)Wg_s;
        for (int i = tid; i < 512; i += 256) d1[i] = s1[i];
        const uint4* s2 = (const uint4*)Wsg; uint4* d2 = (uint4*)Wsg_s;
        for (int i = tid; i < 1024; i += 256) d2[i] = s2[i];
    }
    for (int i = tid; i < 512; i += 256) {
        int row = i >> 3, c8 = i & 7;
        int r = r0 + row;
        uint4 v = make_uint4(0, 0, 0, 0);
        if (r < n) v = *(const uint4*)(aG + r * 32 + c8 * 4);
        int hoff = row * 64 + ((c8 * 8) ^ ((row & 7) << 3));
        *(uint4*)&aG_s[hoff] = v;
    }
    for (int i = tid; i < 1024; i += 256) {
        int row = i >> 4, c8 = i & 15;
        int r = r0 + row;
        uint4 v = make_uint4(0, 0, 0, 0);
        if (r < n) {
            if (c8 < 8) v = *(const uint4*)(aS + r * 32 + c8 * 4);
            else        v = *(const uint4*)(Aprev + (long)r * 32 + (c8 - 8) * 4);
        }
        int hoff = row * 128 + ((c8 * 8) ^ ((row & 7) << 3));
        *(uint4*)&aSh_s[hoff] = v;
    }
    __syncthreads();

    const int w = tid >> 5, lane = tid & 31;
    const int g = lane >> 2, t = lane & 3;
    float c[8][4] = {};
    if (w < 4) {
        int rA = w * 16 + g;
        const unsigned* A32 = (const unsigned*)aG_s;
        const unsigned* B32 = (const unsigned*)Wg_s;
#pragma unroll
        for (int k0 = 0; k0 < 64; k0 += 16) {
            int kw0 = ((k0 >> 1) + t) ^ (g << 2), kw1 = ((k0 >> 1) + t + 4) ^ (g << 2);
            unsigned a0 = A32[rA * 32 + kw0], a1 = A32[(rA + 8) * 32 + kw0];
            unsigned a2 = A32[rA * 32 + kw1], a3 = A32[(rA + 8) * 32 + kw1];
#pragma unroll
            for (int nt = 0; nt < 8; nt++) {
                unsigned b0 = B32[(nt * 8 + g) * 32 + kw0], b1 = B32[(nt * 8 + g) * 32 + kw1];
                MMA16816(c[nt], a0, a1, a2, a3, b0, b1);
            }
        }
        int row0 = r0 + w * 16 + g, row1 = row0 + 8;
        float dv0 = 1.f, dv1 = 1.f;
        if (LAYER == 1) {
            if (row0 < n) dv0 = g_dinv[row0];
            if (row1 < n) dv1 = g_dinv[row1];
        }
#pragma unroll
        for (int nt = 0; nt < 8; nt++) {
            int col = nt * 8 + 2 * t;
            float s0 = escG[col], s1 = escG[col + 1], h0 = eshG[col], h1 = eshG[col + 1];
            c[nt][0] = fmaxf(c[nt][0] * s0 + h0, 0.f);
            c[nt][1] = fmaxf(c[nt][1] * s1 + h1, 0.f);
            c[nt][2] = fmaxf(c[nt][2] * s0 + h0, 0.f);
            c[nt][3] = fmaxf(c[nt][3] * s1 + h1, 0.f);
            if (LAYER == 1) {
                int p = col >> 1;
                int gofs = (p >> 1) * 4 + (p & 1);
                if (row0 < n) hh2u[row0 * 64 + gofs] = pk(c[nt][0] * dv0, c[nt][1] * dv0);
                if (row1 < n) hh2u[row1 * 64 + gofs] = pk(c[nt][2] * dv1, c[nt][3] * dv1);
            }
        }
    } else {
        int rA = (w - 4) * 16 + g;
        const unsigned* A32 = (const unsigned*)aSh_s;
        const unsigned* B32 = (const unsigned*)Wsg_s;
#pragma unroll
        for (int k0 = 0; k0 < 128; k0 += 16) {
            int kw0 = ((k0 >> 1) + t) ^ (g << 2), kw1 = ((k0 >> 1) + t + 4) ^ (g << 2);
            unsigned a0 = A32[rA * 64 + kw0], a1 = A32[(rA + 8) * 64 + kw0];
            unsigned a2 = A32[rA * 64 + kw1], a3 = A32[(rA + 8) * 64 + kw1];
#pragma unroll
            for (int nt = 0; nt < 8; nt++) {
                unsigned b0 = B32[(nt * 8 + g) * 64 + kw0], b1 = B32[(nt * 8 + g) * 64 + kw1];
                MMA16816(c[nt], a0, a1, a2, a3, b0, b1);
            }
        }
        int row0 = r0 + (w - 4) * 16 + g, row1 = row0 + 8;
#pragma unroll
        for (int nt = 0; nt < 8; nt++) {
            int col = nt * 8 + 2 * t;
            float s0 = escS[col], s1 = escS[col + 1], h0 = eshS[col], h1 = eshS[col + 1];
            c[nt][0] = fmaxf(c[nt][0] * s0 + h0, 0.f);
            c[nt][1] = fmaxf(c[nt][1] * s1 + h1, 0.f);
            c[nt][2] = fmaxf(c[nt][2] * s0 + h0, 0.f);
            c[nt][3] = fmaxf(c[nt][3] * s1 + h1, 0.f);
            if (LAYER == 1) {
                int p = col >> 1;
                int gofs = (p >> 1) * 4 + 2 + (p & 1);
                if (row0 < n) {
                    hh2u[row0 * 64 + gofs] = pk(c[nt][0], c[nt][1]);
                    hs16[(long)row0 * 32 + p] = __floats2bfloat162_rn(c[nt][0], c[nt][1]);
                }
                if (row1 < n) {
                    hh2u[row1 * 64 + gofs] = pk(c[nt][2], c[nt][3]);
                    hs16[(long)row1 * 32 + p] = __floats2bfloat162_rn(c[nt][2], c[nt][3]);
                }
            }
        }
    }

    if (LAYER == 2) {
        // stage fp32 post-BN values into SMEM (reuse sbuf), then run-flush pool
        __syncthreads();   // MMA reads of sbuf complete
        float* sG = (float*)sbuf;            // 64x64 fp32 = 16KB
        float* sS = (float*)(sbuf + 16384);  // 64x64 fp32 = 16KB
        float* sp = (w < 4) ? sG : sS;
        int rl = (w < 4 ? w : w - 4) * 16 + g;
#pragma unroll
        for (int nt = 0; nt < 8; nt++) {
            int col = nt * 8 + 2 * t;
            sp[rl * 64 + col]           = c[nt][0];
            sp[rl * 64 + col + 1]       = c[nt][1];
            sp[(rl + 8) * 64 + col]     = c[nt][2];
            sp[(rl + 8) * 64 + col + 1] = c[nt][3];
        }
        __syncthreads();
        int col = tid & 63, q = tid >> 6;        // 4 quarters x 16 rows
        int curg = -1; float accG = 0.f, accS = 0.f;
        for (int rr = q * 16; rr < q * 16 + 16; rr++) {
            int node = r0 + rr;
            if (node >= n) break;
            int gb = batch[node];
            if (gb != curg) {
                if (curg >= 0) {
                    atomicAdd(&g_pool[curg * 128 + col], accG);
                    atomicAdd(&g_pool[curg * 128 + 64 + col], accS);
                }
                curg = gb; accG = 0.f; accS = 0.f;
            }
            accG += sG[rr * 64 + col];
            accS += sS[rr * 64 + col];
        }
        if (curg >= 0) {
            atomicAdd(&g_pool[curg * 128 + col], accG);
            atomicAdd(&g_pool[curg * 128 + 64 + col], accS);
        }
    }
}

// ---------------- final MLP (one block per graph) + deferred zero of pool/gcnt/indeg ----------------
__global__ void k_mlp(const float* __restrict__ fc1W, const float* __restrict__ fc1b,
                      const float* __restrict__ bn1,
                      const float* __restrict__ fc2W, const float* __restrict__ fc2b,
                      const float* __restrict__ bn2,
                      const float* __restrict__ fc3W, const float* __restrict__ fc3b,
                      float* __restrict__ out) {
    int g = blockIdx.x;
    int t = threadIdx.x;  // 64 threads
    __shared__ float z[128];
    __shared__ float s1[64];
    __shared__ float s2[32];
    for (int i = g * 64 + t; i < MAXN; i += MAXG * 64) g_indeg[i] = 0;
    float inv = 1.f / fmaxf((float)g_gcnt[g], 1.f);
    z[t]      = g_pool[g * 128 + t] * inv;
    z[t + 64] = g_pool[g * 128 + 64 + t] * inv;
    __syncthreads();
    g_pool[g * 128 + t] = 0.f;
    g_pool[g * 128 + 64 + t] = 0.f;
    if (t == 0) g_gcnt[g] = 0;
    float acc = fc1b[t];
#pragma unroll 8
    for (int k = 0; k < 128; k++) acc += z[k] * fc1W[k * 64 + t];
    acc = (acc - bn1[128 + t]) * rsqrtf(bn1[192 + t] + EPSBN) * bn1[t] + bn1[64 + t];
    s1[t] = fmaxf(acc, 0.f);
    __syncthreads();
    if (t < 32) {
        float a = fc2b[t];
#pragma unroll 8
        for (int k = 0; k < 64; k++) a += s1[k] * fc2W[k * 32 + t];
        a = (a - bn2[64 + t]) * rsqrtf(bn2[96 + t] + EPSBN) * bn2[t] + bn2[32 + t];
        s2[t] = fmaxf(a, 0.f);
    }
    __syncthreads();
    if (t < 32) {
        float p = s2[t] * fc3W[t];
#pragma unroll
        for (int o = 16; o > 0; o >>= 1) p += __shfl_down_sync(0xffffffffu, p, o);
        if (t == 0) out[g] = p + fc3b[0];
    }
}

// ---------------- launch ----------------
extern "C" void kernel_launch(void* const* d_in, const int* in_sizes, int n_in,
                              void* d_out, int out_size) {
    const float* x     = (const float*)d_in[0];
    const int*   ei    = (const int*)d_in[1];
    const int*   batch = (const int*)d_in[2];
    const float* W_in  = (const float*)d_in[3];
    const float* b_in  = (const float*)d_in[4];
    const float* gcn_W = (const float*)d_in[5];
    const float* gcn_b = (const float*)d_in[6];
    const float* gcn_bn= (const float*)d_in[7];
    const float* sg_Wl = (const float*)d_in[8];
    const float* sg_Wr = (const float*)d_in[9];
    const float* sg_b  = (const float*)d_in[10];
    const float* sg_bn = (const float*)d_in[11];
    const float* fc1W  = (const float*)d_in[12];
    const float* fc1b  = (const float*)d_in[13];
    const float* bn1   = (const float*)d_in[14];
    const float* fc2W  = (const float*)d_in[15];
    const float* fc2b  = (const float*)d_in[16];
    const float* bn2   = (const float*)d_in[17];
    const float* fc3W  = (const float*)d_in[18];
    const float* fc3b  = (const float*)d_in[19];
    float* out = (float*)d_out;

    int N = in_sizes[0] / DIN;
    int E = in_sizes[1] / 2;
    const int* src = ei;
    const int* dst = ei + E;

    __nv_bfloat162 *d_h16, *d_hs16, *d_aG, *d_aS;
    uint4 *d_h2x, *d_hh2x;
    __nv_bfloat16* d_Wt;
    float *d_esc, *d_esh;
    cudaGetSymbolAddress((void**)&d_h16,  g_h16);
    cudaGetSymbolAddress((void**)&d_hs16, g_hs16);
    cudaGetSymbolAddress((void**)&d_h2x,  g_h2x);
    cudaGetSymbolAddress((void**)&d_hh2x, g_hh2x);
    cudaGetSymbolAddress((void**)&d_aG,   g_aG16);
    cudaGetSymbolAddress((void**)&d_aS,   g_aS16);
    cudaGetSymbolAddress((void**)&d_Wt,   g_Wt);
    cudaGetSymbolAddress((void**)&d_esc,  g_esc);
    cudaGetSymbolAddress((void**)&d_esh,  g_esh);

    int nbN   = (N + 255) / 256;
    int nbE   = ((E > N ? E : N) + 255) / 256;
    int nb64  = (N + 63) / 64;
    int nbM   = (N + 63) / 64;
    int nbF   = (E + 255) / 256;
    int nbAgg = (N + 15) / 16;

    // CSR degree count + weight prep (counters pre-zeroed by previous launch / BSS)
    k_deg_prep<<<nbE, 256>>>(dst, batch, W_in, gcn_W, sg_Wl, sg_Wr,
                             b_in, gcn_b, gcn_bn, sg_b, sg_bn, E, N);
    k_scan1<<<nbN, 256>>>(N);
    k_scanB<<<nbN, 256>>>(nbN, N);

    // fused: input projection (interleaved h2x + plain h16) + CSR fill
    k_fill_mma<<<nbM + nbF, 256>>>(src, dst, E, nbM, x, d_Wt, d_esc, d_esh,
                                   (unsigned*)d_h2x, d_h16, N);

    // layer 1: single-load dual-stream gather, then dual GEMM -> hh2x + hs16
    k_agg1<<<nbAgg, 256>>>(d_h2x, d_aG, d_aS, N);
    k_mma_dual<1><<<nb64, 256>>>(d_aG, d_aS, d_h16,
                                 (unsigned*)d_hh2x, d_hs16,
                                 d_Wt + 8192, d_Wt + 16384,
                                 d_esc + 64, d_esh + 64, d_esc + 192, d_esh + 192,
                                 batch, N);
    // layer 2: same gather trick, dual GEMM with fused per-graph pooling
    k_agg2<<<nbAgg, 256>>>(d_hh2x, d_aG, d_aS, N);
    k_mma_dual<2><<<nb64, 256>>>(d_aG, d_aS, d_hs16,
                                 nullptr, nullptr,
                                 d_Wt + 12288, d_Wt + 24576,
                                 d_esc + 128, d_esh + 128, d_esc + 256, d_esh + 256,
                                 batch, N);

    // MLP head (+ deferred re-zeroing of counters/pool)
    k_mlp<<<MAXG, 64>>>(fc1W, fc1b, bn1, fc2W, fc2b, bn2, fc3W, fc3b, out);
}

// round 17
// speedup vs baseline: 1.5090x; 1.5090x over previous
#include <cuda_runtime.h>
#include <cuda_bf16.h>
#include <math.h>

#define H      64
#define DIN    128
#define EPSBN  1e-5f
#define MAXN   50048
#define MAXE   1200128
#define MAXG   64

// ---------------- scratch (static __device__, no runtime allocs) ----------------
// Invariant: g_indeg, g_pool, g_gcnt are ZERO at entry to kernel_launch and are
// re-zeroed before the launch ends (deferred zeroing).
__device__ __nv_bfloat162 g_h16 [MAXN * 32];  // relu(x@W_in)
__device__ __nv_bfloat162 g_hh  [MAXN * 64];  // L1 out interleaved: [hg(prescaled) | hs]
__device__ __nv_bfloat162 g_aG16[MAXN * 32];  // gcn agg scratch
__device__ __nv_bfloat162 g_aS16[MAXN * 32];  // sage agg scratch
__device__ __nv_bfloat16  g_Wt  [32768];      // prepped weights (transposed+swizzled bf16)
__device__ float g_esc[320], g_esh[320];      // epilogue scale/shift
__device__ int   g_indeg[MAXN];
__device__ int   g_epos [MAXE];               // edge slot within its dst row
__device__ int   g_rowptr[MAXN + 1];
__device__ int   g_col  [MAXE];
__device__ float g_dinv [MAXN];
__device__ float g_pool [MAXG * 2 * H];
__device__ int   g_gcnt [MAXG];
__device__ int   g_scanbuf[MAXN];
__device__ int   g_blocksums[256];

// ---------------- deg (+ edge slot) + weight prep + epilogue consts ----------------
__global__ void k_deg_prep(const int* __restrict__ dst, const int* __restrict__ batch,
                           const float* __restrict__ W_in, const float* __restrict__ gcn_W,
                           const float* __restrict__ sg_Wl, const float* __restrict__ sg_Wr,
                           const float* __restrict__ b_in, const float* __restrict__ gcn_b,
                           const float* __restrict__ gcn_bn, const float* __restrict__ sg_b,
                           const float* __restrict__ sg_bn, int E, int N) {
    int i = blockIdx.x * 256 + threadIdx.x;
    if (i < E) g_epos[i] = atomicAdd(&g_indeg[dst[i]], 1);
    if (i < N) atomicAdd(&g_gcnt[batch[i]], 1);
    if (i < 32768) {
        int e = i, nn, k, K, base; float w;
        if (e < 8192)       { K = 128; base = 0;     nn = e >> 7; k = e & 127; w = W_in[k * 64 + nn]; }
        else if (e < 12288) { K = 64;  base = 8192;  int l = e - 8192;  nn = l >> 6; k = l & 63;  w = gcn_W[k * 64 + nn]; }
        else if (e < 16384) { K = 64;  base = 12288; int l = e - 12288; nn = l >> 6; k = l & 63;  w = gcn_W[4096 + k * 64 + nn]; }
        else if (e < 24576) { K = 128; base = 16384; int l = e - 16384; nn = l >> 7; k = l & 127;
                              w = (k < 64) ? sg_Wl[k * 64 + nn] : sg_Wr[(k - 64) * 64 + nn]; }
        else                { K = 128; base = 24576; int l = e - 24576; nn = l >> 7; k = l & 127;
                              w = (k < 64) ? sg_Wl[4096 + k * 64 + nn] : sg_Wr[4096 + (k - 64) * 64 + nn]; }
        int word = (k >> 1) ^ ((nn & 7) << 2);
        g_Wt[base + nn * K + word * 2 + (k & 1)] = __float2bfloat16(w);
    }
    if (blockIdx.x == 0 && threadIdx.x < 64) {
        int c = threadIdx.x;
        g_esc[c] = 1.f; g_esh[c] = b_in[c];
        for (int l = 0; l < 2; l++) {
            const float* bn = gcn_bn + l * 256;
            float sc = bn[c] * rsqrtf(bn[192 + c] + EPSBN);
            g_esc[(1 + l) * 64 + c] = sc;
            g_esh[(1 + l) * 64 + c] = (gcn_b[l * 64 + c] - bn[128 + c]) * sc + bn[64 + c];
            const float* bs = sg_bn + l * 256;
            float sc2 = bs[c] * rsqrtf(bs[192 + c] + EPSBN);
            g_esc[(3 + l) * 64 + c] = sc2;
            g_esh[(3 + l) * 64 + c] = (sg_b[l * 64 + c] - bs[128 + c]) * sc2 + bs[64 + c];
        }
    }
}

// ---------------- two-pass scan (parallel, no cross-block waits) ----------------
__global__ void k_scan1(int N) {
    __shared__ int sh[256];
    int t = threadIdx.x;
    int i = blockIdx.x * 256 + t;
    int v = (i < N) ? g_indeg[i] : 0;
    sh[t] = v; __syncthreads();
#pragma unroll
    for (int off = 1; off < 256; off <<= 1) {
        int a = 0;
        if (t >= off) a = sh[t - off];
        __syncthreads();
        sh[t] += a;
        __syncthreads();
    }
    if (i < N) {
        g_scanbuf[i] = sh[t];
        g_dinv[i] = rsqrtf((float)(v + 1));
    }
    if (t == 255) g_blocksums[blockIdx.x] = sh[255];
}

__global__ void k_scanB(int nb, int N) {
    __shared__ int sh[256];
    int t = threadIdx.x;
    int v = (t < nb) ? g_blocksums[t] : 0;
    sh[t] = v; __syncthreads();
#pragma unroll
    for (int off = 1; off < 256; off <<= 1) {
        int a = 0;
        if (t >= off) a = sh[t - off];
        __syncthreads();
        sh[t] += a;
        __syncthreads();
    }
    int myoff = sh[blockIdx.x] - g_blocksums[blockIdx.x];
    int i = blockIdx.x * 256 + t;
    if (i < N) g_rowptr[i + 1] = g_scanbuf[i] + myoff;
    if (i == 0) g_rowptr[0] = 0;
}

// ---------------- mma asm helper ----------------
#define MMA16816(c, a0, a1, a2, a3, b0, b1) \
    asm volatile( \
        "mma.sync.aligned.m16n8k16.row.col.f32.bf16.bf16.f32 " \
        "{%0,%1,%2,%3}, {%4,%5,%6,%7}, {%8,%9}, {%0,%1,%2,%3};" \
        : "+f"((c)[0]), "+f"((c)[1]), "+f"((c)[2]), "+f"((c)[3]) \
        : "r"(a0), "r"(a1), "r"(a2), "r"(a3), "r"(b0), "r"(b1))

// ---------------- fused: CSR fill + input projection (independent work) ----------------
// Blocks [0, nbM): h16 = relu(x @ W_in + b_in), BM=128, B-fragments from global (L1-hot).
// Blocks [nbM, ...): CSR fill (no atomics; slot captured during degree counting).
__global__ void __launch_bounds__(256)
k_fill_mma(const int* __restrict__ src, const int* __restrict__ dst, int E, int nbM,
           const float* __restrict__ X, const __nv_bfloat16* __restrict__ Wt,
           const float* __restrict__ esc, const float* __restrict__ esh,
           __nv_bfloat162* __restrict__ out16, int n) {
    __shared__ __align__(16) __nv_bfloat16 As[128 * 128];
    if ((int)blockIdx.x >= nbM) {
        int e = (blockIdx.x - nbM) * 256 + threadIdx.x;
        if (e < E) {
            int d = dst[e];
            g_col[g_rowptr[d] + g_epos[e]] = src[e];
        }
        return;
    }
    const int tid = threadIdx.x;
    const int r0 = blockIdx.x * 128;
    for (int i = tid; i < 128 * 32; i += 256) {
        int row = i >> 5, c4 = i & 31;
        int r = r0 + row;
        float4 v = make_float4(0.f, 0.f, 0.f, 0.f);
        if (r < n) v = *(const float4*)(X + (long)r * 128 + c4 * 4);
        int hoff = row * 128 + ((c4 * 4) ^ ((row & 7) << 3));
        __nv_bfloat162* p = (__nv_bfloat162*)&As[hoff];
        p[0] = __floats2bfloat162_rn(v.x, v.y);
        p[1] = __floats2bfloat162_rn(v.z, v.w);
    }
    __syncthreads();
    const int w = tid >> 5, lane = tid & 31;
    const int g = lane >> 2, t = lane & 3;
    const int rA = w * 16 + g;
    const unsigned* A32 = (const unsigned*)As;
    const unsigned* B32 = (const unsigned*)Wt;  // global, stays hot in L1
    float c[8][4] = {};
#pragma unroll
    for (int k0 = 0; k0 < 128; k0 += 16) {
        int kw0 = ((k0 >> 1) + t) ^ (g << 2), kw1 = ((k0 >> 1) + t + 4) ^ (g << 2);
        unsigned a0 = A32[rA * 64 + kw0], a1 = A32[(rA + 8) * 64 + kw0];
        unsigned a2 = A32[rA * 64 + kw1], a3 = A32[(rA + 8) * 64 + kw1];
#pragma unroll
        for (int nt = 0; nt < 8; nt++) {
            unsigned b0 = B32[(nt * 8 + g) * 64 + kw0], b1 = B32[(nt * 8 + g) * 64 + kw1];
            MMA16816(c[nt], a0, a1, a2, a3, b0, b1);
        }
    }
    int row0 = r0 + w * 16 + g, row1 = row0 + 8;
#pragma unroll
    for (int nt = 0; nt < 8; nt++) {
        int col = nt * 8 + 2 * t;
        float s0 = esc[col], s1 = esc[col + 1], h0 = esh[col], h1 = esh[col + 1];
        float v00 = fmaxf(c[nt][0] * s0 + h0, 0.f);
        float v01 = fmaxf(c[nt][1] * s1 + h1, 0.f);
        float v10 = fmaxf(c[nt][2] * s0 + h0, 0.f);
        float v11 = fmaxf(c[nt][3] * s1 + h1, 0.f);
        if (row0 < n) out16[row0 * 32 + (col >> 1)] = __floats2bfloat162_rn(v00, v01);
        if (row1 < n) out16[row1 * 32 + (col >> 1)] = __floats2bfloat162_rn(v10, v11);
    }
}

// ---------------- aggregations: 16 lanes per node, 2 nodes per warp ----------------
// Layer 1: aG[d] = dinv_d*(sum dinv_s*h_s + dinv_d*h_d);  aS[d] = mean h_s
__global__ void __launch_bounds__(256)
k_agg1(const __nv_bfloat162* __restrict__ h16,
       __nv_bfloat162* __restrict__ aG, __nv_bfloat162* __restrict__ aS, int n) {
    int warp = threadIdx.x >> 5, lane = threadIdx.x & 31;
    int half = lane >> 4, l = lane & 15;
    int d = blockIdx.x * 16 + warp * 2 + half;
    bool dok = d < n;
    int beg = 0, end = 0;
    if (dok) { beg = g_rowptr[d]; end = g_rowptr[d + 1]; }
    int cnt = end - beg;
    int mc = __reduce_max_sync(0xffffffffu, cnt);
    const uint2* h2 = (const uint2*)h16;
    float g0 = 0.f, g1 = 0.f, g2 = 0.f, g3 = 0.f;
    float s0 = 0.f, s1 = 0.f, s2 = 0.f, s3 = 0.f;
    for (int k = 0; k < mc; k += 8) {
#pragma unroll
        for (int u = 0; u < 8; u++) {
            int idx = k + u;
            bool v = idx < cnt;
            int s = 0;
            if (v) s = g_col[beg + idx];
            float ww = v ? g_dinv[s] : 0.f;
            float vm = v ? 1.f : 0.f;
            uint2 r = h2[s * 16 + l];
            float2 f0 = __bfloat1622float2(*(__nv_bfloat162*)&r.x);
            float2 f1 = __bfloat1622float2(*(__nv_bfloat162*)&r.y);
            g0 += ww * f0.x; g1 += ww * f0.y; g2 += ww * f1.x; g3 += ww * f1.y;
            s0 += vm * f0.x; s1 += vm * f0.y; s2 += vm * f1.x; s3 += vm * f1.y;
        }
    }
    if (!dok) return;
    float wd = g_dinv[d];
    uint2 rd = h2[d * 16 + l];
    float2 fd0 = __bfloat1622float2(*(__nv_bfloat162*)&rd.x);
    float2 fd1 = __bfloat1622float2(*(__nv_bfloat162*)&rd.y);
    g0 = (g0 + wd * fd0.x) * wd; g1 = (g1 + wd * fd0.y) * wd;
    g2 = (g2 + wd * fd1.x) * wd; g3 = (g3 + wd * fd1.y) * wd;
    float inv = 1.f / fmaxf((float)cnt, 1.f);
    uint2 og, os;
    *(__nv_bfloat162*)&og.x = __floats2bfloat162_rn(g0, g1);
    *(__nv_bfloat162*)&og.y = __floats2bfloat162_rn(g2, g3);
    *(__nv_bfloat162*)&os.x = __floats2bfloat162_rn(s0 * inv, s1 * inv);
    *(__nv_bfloat162*)&os.y = __floats2bfloat162_rn(s2 * inv, s3 * inv);
    ((uint2*)aG)[d * 16 + l] = og;
    ((uint2*)aS)[d * 16 + l] = os;
}

// Layer 2: hh = [hg(prescaled)|hs] interleaved (32 uint2/row). Unroll 4 (R12 lesson).
__global__ void __launch_bounds__(256)
k_agg2(const __nv_bfloat162* __restrict__ hh,
       __nv_bfloat162* __restrict__ aG, __nv_bfloat162* __restrict__ aS, int n) {
    int warp = threadIdx.x >> 5, lane = threadIdx.x & 31;
    int half = lane >> 4, l = lane & 15;
    int d = blockIdx.x * 16 + warp * 2 + half;
    bool dok = d < n;
    int beg = 0, end = 0;
    if (dok) { beg = g_rowptr[d]; end = g_rowptr[d + 1]; }
    int cnt = end - beg;
    int mc = __reduce_max_sync(0xffffffffu, cnt);
    const uint2* h2 = (const uint2*)hh;
    float g0 = 0.f, g1 = 0.f, g2 = 0.f, g3 = 0.f;
    float s0 = 0.f, s1 = 0.f, s2 = 0.f, s3 = 0.f;
    for (int k = 0; k < mc; k += 4) {
#pragma unroll
        for (int u = 0; u < 4; u++) {
            int idx = k + u;
            bool v = idx < cnt;
            int s = 0;
            if (v) s = g_col[beg + idx];
            float vm = v ? 1.f : 0.f;
            uint2 ra = h2[s * 32 + l];
            uint2 rb = h2[s * 32 + 16 + l];
            float2 a0 = __bfloat1622float2(*(__nv_bfloat162*)&ra.x);
            float2 a1 = __bfloat1622float2(*(__nv_bfloat162*)&ra.y);
            float2 b0 = __bfloat1622float2(*(__nv_bfloat162*)&rb.x);
            float2 b1 = __bfloat1622float2(*(__nv_bfloat162*)&rb.y);
            g0 += vm * a0.x; g1 += vm * a0.y; g2 += vm * a1.x; g3 += vm * a1.y;
            s0 += vm * b0.x; s1 += vm * b0.y; s2 += vm * b1.x; s3 += vm * b1.y;
        }
    }
    if (!dok) return;
    float wd = g_dinv[d];
    uint2 rd = h2[d * 32 + l];
    float2 ad0 = __bfloat1622float2(*(__nv_bfloat162*)&rd.x);
    float2 ad1 = __bfloat1622float2(*(__nv_bfloat162*)&rd.y);
    g0 = (g0 + ad0.x) * wd; g1 = (g1 + ad0.y) * wd;
    g2 = (g2 + ad1.x) * wd; g3 = (g3 + ad1.y) * wd;
    float inv = 1.f / fmaxf((float)cnt, 1.f);
    uint2 og, os;
    *(__nv_bfloat162*)&og.x = __floats2bfloat162_rn(g0, g1);
    *(__nv_bfloat162*)&og.y = __floats2bfloat162_rn(g2, g3);
    *(__nv_bfloat162*)&os.x = __floats2bfloat162_rn(s0 * inv, s1 * inv);
    *(__nv_bfloat162*)&os.y = __floats2bfloat162_rn(s2 * inv, s3 * inv);
    ((uint2*)aG)[d * 16 + l] = og;
    ((uint2*)aS)[d * 16 + l] = os;
}

// ---------------- dual MMA: warps 0-3 GCN (K=64), warps 4-7 SAGE (K=128) ----------------
// LAYER==1: writes interleaved hh (GCN prescaled by dinv).
// LAYER==2: no gmem feature output; pools post-BN fp32 values per graph (batch sorted).
template<int LAYER>
__global__ void __launch_bounds__(256)
k_mma_dual(const __nv_bfloat162* __restrict__ aG,
           const __nv_bfloat162* __restrict__ aS,
           const __nv_bfloat162* __restrict__ Aprev, int strideAp,
           __nv_bfloat162* __restrict__ outG, int strideG,
           __nv_bfloat162* __restrict__ outS, int strideS,
           const __nv_bfloat16* __restrict__ Wg,
           const __nv_bfloat16* __restrict__ Wsg,
           const float* __restrict__ escG, const float* __restrict__ eshG,
           const float* __restrict__ escS, const float* __restrict__ eshS,
           const int* __restrict__ batch, int n) {
    __shared__ __align__(16) char sbuf[49152];
    __nv_bfloat16* aG_s  = (__nv_bfloat16*)sbuf;            // 8KB
    __nv_bfloat16* aSh_s = (__nv_bfloat16*)(sbuf + 8192);   // 16KB
    __nv_bfloat16* Wg_s  = (__nv_bfloat16*)(sbuf + 24576);  // 8KB
    __nv_bfloat16* Wsg_s = (__nv_bfloat16*)(sbuf + 32768);  // 16KB
    const int tid = threadIdx.x;
    const int r0 = blockIdx.x * 64;

    {
        const uint4* s1 = (const uint4*)Wg;  uint4* d1 = (uint4*)Wg_s;
        for (int i = tid; i < 512; i += 256) d1[i] = s1[i];
        const uint4* s2 = (const uint4*)Wsg; uint4* d2 = (uint4*)Wsg_s;
        for (int i = tid; i < 1024; i += 256) d2[i] = s2[i];
    }
    for (int i = tid; i < 512; i += 256) {
        int row = i >> 3, c8 = i & 7;
        int r = r0 + row;
        uint4 v = make_uint4(0, 0, 0, 0);
        if (r < n) v = *(const uint4*)(aG + r * 32 + c8 * 4);
        int hoff = row * 64 + ((c8 * 8) ^ ((row & 7) << 3));
        *(uint4*)&aG_s[hoff] = v;
    }
    for (int i = tid; i < 1024; i += 256) {
        int row = i >> 4, c8 = i & 15;
        int r = r0 + row;
        uint4 v = make_uint4(0, 0, 0, 0);
        if (r < n) {
            if (c8 < 8) v = *(const uint4*)(aS + r * 32 + c8 * 4);
            else        v = *(const uint4*)(Aprev + (long)r * strideAp + (c8 - 8) * 4);
        }
        int hoff = row * 128 + ((c8 * 8) ^ ((row & 7) << 3));
        *(uint4*)&aSh_s[hoff] = v;
    }
    __syncthreads();

    const int w = tid >> 5, lane = tid & 31;
    const int g = lane >> 2, t = lane & 3;
    float c[8][4] = {};
    if (w < 4) {
        int rA = w * 16 + g;
        const unsigned* A32 = (const unsigned*)aG_s;
        const unsigned* B32 = (const unsigned*)Wg_s;
#pragma unroll
        for (int k0 = 0; k0 < 64; k0 += 16) {
            int kw0 = ((k0 >> 1) + t) ^ (g << 2), kw1 = ((k0 >> 1) + t + 4) ^ (g << 2);
            unsigned a0 = A32[rA * 32 + kw0], a1 = A32[(rA + 8) * 32 + kw0];
            unsigned a2 = A32[rA * 32 + kw1], a3 = A32[(rA + 8) * 32 + kw1];
#pragma unroll
            for (int nt = 0; nt < 8; nt++) {
                unsigned b0 = B32[(nt * 8 + g) * 32 + kw0], b1 = B32[(nt * 8 + g) * 32 + kw1];
                MMA16816(c[nt], a0, a1, a2, a3, b0, b1);
            }
        }
        int row0 = r0 + w * 16 + g, row1 = row0 + 8;
        float dv0 = 1.f, dv1 = 1.f;
        if (LAYER == 1) {
            if (row0 < n) dv0 = g_dinv[row0];
            if (row1 < n) dv1 = g_dinv[row1];
        }
#pragma unroll
        for (int nt = 0; nt < 8; nt++) {
            int col = nt * 8 + 2 * t;
            float s0 = escG[col], s1 = escG[col + 1], h0 = eshG[col], h1 = eshG[col + 1];
            c[nt][0] = fmaxf(c[nt][0] * s0 + h0, 0.f);
            c[nt][1] = fmaxf(c[nt][1] * s1 + h1, 0.f);
            c[nt][2] = fmaxf(c[nt][2] * s0 + h0, 0.f);
            c[nt][3] = fmaxf(c[nt][3] * s1 + h1, 0.f);
            if (LAYER == 1) {
                if (row0 < n) outG[(long)row0 * strideG + (col >> 1)] =
                    __floats2bfloat162_rn(c[nt][0] * dv0, c[nt][1] * dv0);
                if (row1 < n) outG[(long)row1 * strideG + (col >> 1)] =
                    __floats2bfloat162_rn(c[nt][2] * dv1, c[nt][3] * dv1);
            }
        }
    } else {
        int rA = (w - 4) * 16 + g;
        const unsigned* A32 = (const unsigned*)aSh_s;
        const unsigned* B32 = (const unsigned*)Wsg_s;
#pragma unroll
        for (int k0 = 0; k0 < 128; k0 += 16) {
            int kw0 = ((k0 >> 1) + t) ^ (g << 2), kw1 = ((k0 >> 1) + t + 4) ^ (g << 2);
            unsigned a0 = A32[rA * 64 + kw0], a1 = A32[(rA + 8) * 64 + kw0];
            unsigned a2 = A32[rA * 64 + kw1], a3 = A32[(rA + 8) * 64 + kw1];
#pragma unroll
            for (int nt = 0; nt < 8; nt++) {
                unsigned b0 = B32[(nt * 8 + g) * 64 + kw0], b1 = B32[(nt * 8 + g) * 64 + kw1];
                MMA16816(c[nt], a0, a1, a2, a3, b0, b1);
            }
        }
        int row0 = r0 + (w - 4) * 16 + g, row1 = row0 + 8;
#pragma unroll
        for (int nt = 0; nt < 8; nt++) {
            int col = nt * 8 + 2 * t;
            float s0 = escS[col], s1 = escS[col + 1], h0 = eshS[col], h1 = eshS[col + 1];
            c[nt][0] = fmaxf(c[nt][0] * s0 + h0, 0.f);
            c[nt][1] = fmaxf(c[nt][1] * s1 + h1, 0.f);
            c[nt][2] = fmaxf(c[nt][2] * s0 + h0, 0.f);
            c[nt][3] = fmaxf(c[nt][3] * s1 + h1, 0.f);
            if (LAYER == 1) {
                if (row0 < n) outS[(long)row0 * strideS + (col >> 1)] =
                    __floats2bfloat162_rn(c[nt][0], c[nt][1]);
                if (row1 < n) outS[(long)row1 * strideS + (col >> 1)] =
                    __floats2bfloat162_rn(c[nt][2], c[nt][3]);
            }
        }
    }

    if (LAYER == 2) {
        // stage fp32 post-BN values into SMEM (reuse sbuf), then run-flush pool
        __syncthreads();   // MMA reads of sbuf complete
        float* sG = (float*)sbuf;            // 64x64 fp32 = 16KB
        float* sS = (float*)(sbuf + 16384);  // 64x64 fp32 = 16KB
        float* sp = (w < 4) ? sG : sS;
        int rl = (w < 4 ? w : w - 4) * 16 + g;
#pragma unroll
        for (int nt = 0; nt < 8; nt++) {
            int col = nt * 8 + 2 * t;
            sp[rl * 64 + col]           = c[nt][0];
            sp[rl * 64 + col + 1]       = c[nt][1];
            sp[(rl + 8) * 64 + col]     = c[nt][2];
            sp[(rl + 8) * 64 + col + 1] = c[nt][3];
        }
        __syncthreads();
        int col = tid & 63, q = tid >> 6;        // 4 quarters x 16 rows
        int curg = -1; float accG = 0.f, accS = 0.f;
        for (int rr = q * 16; rr < q * 16 + 16; rr++) {
            int node = r0 + rr;
            if (node >= n) break;
            int gb = batch[node];
            if (gb != curg) {
                if (curg >= 0) {
                    atomicAdd(&g_pool[curg * 128 + col], accG);
                    atomicAdd(&g_pool[curg * 128 + 64 + col], accS);
                }
                curg = gb; accG = 0.f; accS = 0.f;
            }
            accG += sG[rr * 64 + col];
            accS += sS[rr * 64 + col];
        }
        if (curg >= 0) {
            atomicAdd(&g_pool[curg * 128 + col], accG);
            atomicAdd(&g_pool[curg * 128 + 64 + col], accS);
        }
    }
}

// ---------------- final MLP (one block per graph) + deferred zero of pool/gcnt/indeg ----------------
__global__ void k_mlp(const float* __restrict__ fc1W, const float* __restrict__ fc1b,
                      const float* __restrict__ bn1,
                      const float* __restrict__ fc2W, const float* __restrict__ fc2b,
                      const float* __restrict__ bn2,
                      const float* __restrict__ fc3W, const float* __restrict__ fc3b,
                      float* __restrict__ out) {
    int g = blockIdx.x;
    int t = threadIdx.x;  // 64 threads
    __shared__ float z[128];
    __shared__ float s1[64];
    __shared__ float s2[32];
    // deferred re-zero of CSR degree counters (fully consumed earlier this launch)
    for (int i = g * 64 + t; i < MAXN; i += MAXG * 64) g_indeg[i] = 0;
    float inv = 1.f / fmaxf((float)g_gcnt[g], 1.f);
    z[t]      = g_pool[g * 128 + t] * inv;
    z[t + 64] = g_pool[g * 128 + 64 + t] * inv;
    __syncthreads();
    g_pool[g * 128 + t] = 0.f;
    g_pool[g * 128 + 64 + t] = 0.f;
    if (t == 0) g_gcnt[g] = 0;
    float acc = fc1b[t];
#pragma unroll 8
    for (int k = 0; k < 128; k++) acc += z[k] * fc1W[k * 64 + t];
    acc = (acc - bn1[128 + t]) * rsqrtf(bn1[192 + t] + EPSBN) * bn1[t] + bn1[64 + t];
    s1[t] = fmaxf(acc, 0.f);
    __syncthreads();
    if (t < 32) {
        float a = fc2b[t];
#pragma unroll 8
        for (int k = 0; k < 64; k++) a += s1[k] * fc2W[k * 32 + t];
        a = (a - bn2[64 + t]) * rsqrtf(bn2[96 + t] + EPSBN) * bn2[t] + bn2[32 + t];
        s2[t] = fmaxf(a, 0.f);
    }
    __syncthreads();
    if (t < 32) {
        float p = s2[t] * fc3W[t];
#pragma unroll
        for (int o = 16; o > 0; o >>= 1) p += __shfl_down_sync(0xffffffffu, p, o);
        if (t == 0) out[g] = p + fc3b[0];
    }
}

// ---------------- launch ----------------
extern "C" void kernel_launch(void* const* d_in, const int* in_sizes, int n_in,
                              void* d_out, int out_size) {
    const float* x     = (const float*)d_in[0];
    const int*   ei    = (const int*)d_in[1];
    const int*   batch = (const int*)d_in[2];
    const float* W_in  = (const float*)d_in[3];
    const float* b_in  = (const float*)d_in[4];
    const float* gcn_W = (const float*)d_in[5];
    const float* gcn_b = (const float*)d_in[6];
    const float* gcn_bn= (const float*)d_in[7];
    const float* sg_Wl = (const float*)d_in[8];
    const float* sg_Wr = (const float*)d_in[9];
    const float* sg_b  = (const float*)d_in[10];
    const float* sg_bn = (const float*)d_in[11];
    const float* fc1W  = (const float*)d_in[12];
    const float* fc1b  = (const float*)d_in[13];
    const float* bn1   = (const float*)d_in[14];
    const float* fc2W  = (const float*)d_in[15];
    const float* fc2b  = (const float*)d_in[16];
    const float* bn2   = (const float*)d_in[17];
    const float* fc3W  = (const float*)d_in[18];
    const float* fc3b  = (const float*)d_in[19];
    float* out = (float*)d_out;

    int N = in_sizes[0] / DIN;
    int E = in_sizes[1] / 2;
    const int* src = ei;
    const int* dst = ei + E;

    __nv_bfloat162 *d_h16, *d_hh, *d_aG, *d_aS;
    __nv_bfloat16* d_Wt;
    float *d_esc, *d_esh;
    cudaGetSymbolAddress((void**)&d_h16, g_h16);
    cudaGetSymbolAddress((void**)&d_hh,  g_hh);
    cudaGetSymbolAddress((void**)&d_aG,  g_aG16);
    cudaGetSymbolAddress((void**)&d_aS,  g_aS16);
    cudaGetSymbolAddress((void**)&d_Wt,  g_Wt);
    cudaGetSymbolAddress((void**)&d_esc, g_esc);
    cudaGetSymbolAddress((void**)&d_esh, g_esh);

    int nbN   = (N + 255) / 256;
    int nbE   = ((E > N ? E : N) + 255) / 256;
    int nb64  = (N + 63) / 64;
    int nbM   = (N + 127) / 128;
    int nbF   = (E + 255) / 256;
    int nbAgg = (N + 15) / 16;

    // CSR degree count + weight prep (counters pre-zeroed by previous launch / BSS)
    k_deg_prep<<<nbE, 256>>>(dst, batch, W_in, gcn_W, sg_Wl, sg_Wr,
                             b_in, gcn_b, gcn_bn, sg_b, sg_bn, E, N);
    k_scan1<<<nbN, 256>>>(N);
    k_scanB<<<nbN, 256>>>(nbN, N);

    // fused: input projection (independent) + CSR fill
    k_fill_mma<<<nbM + nbF, 256>>>(src, dst, E, nbM, x, d_Wt, d_esc, d_esh, d_h16, N);

    // layer 1: agg then dual GEMM -> interleaved g_hh [hg|hs]
    k_agg1<<<nbAgg, 256>>>(d_h16, d_aG, d_aS, N);
    k_mma_dual<1><<<nb64, 256>>>(d_aG, d_aS, d_h16, 32,
                                 d_hh, 64, d_hh + 32, 64,
                                 d_Wt + 8192, d_Wt + 16384,
                                 d_esc + 64, d_esh + 64, d_esc + 192, d_esh + 192,
                                 batch, N);
    // layer 2: agg then dual GEMM with fused per-graph pooling
    k_agg2<<<nbAgg, 256>>>(d_hh, d_aG, d_aS, N);
    k_mma_dual<2><<<nb64, 256>>>(d_aG, d_aS, d_hh + 32, 64,
                                 nullptr, 0, nullptr, 0,
                                 d_Wt + 12288, d_Wt + 24576,
                                 d_esc + 128, d_esh + 128, d_esc + 256, d_esh + 256,
                                 batch, N);

    // MLP head (+ deferred re-zeroing of counters/pool)
    k_mlp<<<MAXG, 64>>>(fc1W, fc1b, bn1, fc2W, fc2b, bn2, fc3W, fc3b, out);
}